// round 11
// baseline (speedup 1.0000x reference)
#include <cuda_runtime.h>
#include <stdint.h>

#define BSZ  16384
#define KC   8192
#define MAXC 100
#define MINC 20
#define NT   256
#define PER  32
#define CAP  512
#define KTHR 0x3FDFFFFFu   // fkey(-2.5f): prefilter threshold in key space

__device__ __forceinline__ uint32_t fkey(uint32_t u) {
    return u ^ (uint32_t)(((int)u >> 31) | (int)0x80000000);   // order-preserving
}

// sum over threads with tid' > tid (block exclusive suffix). 2 barriers.
__device__ __forceinline__ int block_suffix_excl(int v, int tid, volatile int* wtmp) {
    int lane = tid & 31, w = tid >> 5;
    int x = v;
    #pragma unroll
    for (int off = 1; off < 32; off <<= 1) {
        int t = __shfl_down_sync(0xFFFFFFFFu, x, off);
        if (lane + off < 32) x += t;
    }
    if (lane == 0) wtmp[w] = x;
    __syncthreads();
    int above = 0;
    #pragma unroll
    for (int j = 0; j < 8; j++) above += (j > w) ? wtmp[j] : 0;
    __syncthreads();
    return above + (x - v);
}

// sum over threads with tid' < tid (block exclusive prefix). 2 barriers.
__device__ __forceinline__ int block_prefix_excl(int v, int tid, volatile int* wtmp) {
    int lane = tid & 31, w = tid >> 5;
    int x = v;
    #pragma unroll
    for (int off = 1; off < 32; off <<= 1) {
        int t = __shfl_up_sync(0xFFFFFFFFu, x, off);
        if (lane >= off) x += t;
    }
    if (lane == 31) wtmp[w] = x;
    __syncthreads();
    int below = 0;
    #pragma unroll
    for (int j = 0; j < 8; j++) below += (j < w) ? wtmp[j] : 0;
    __syncthreads();
    return below + (x - v);
}

struct Sel { uint32_t T; int need_eq; };

// Select rank-k largest among W candidates in ckey[] via 3 histogram passes.
// hist[] must be all-zero on entry; leaves it all-zero on exit.
__device__ __forceinline__ Sel refine_T(
    const uint32_t* ckey, int W, int k, int tid,
    int* hist, volatile int* wtmp, int* sctl /* [4]: b,need,d,need2 */)
{
    const int4 z4 = make_int4(0, 0, 0, 0);
    // pass A: top 11 bits
    for (int i = tid; i < W; i += NT) atomicAdd(&hist[ckey[i] >> 21], 1);
    __syncthreads();
    int h[8];
    {
        int4 a = ((int4*)hist)[2 * tid];
        int4 bb = ((int4*)hist)[2 * tid + 1];
        h[0] = a.x; h[1] = a.y; h[2] = a.z; h[3] = a.w;
        h[4] = bb.x; h[5] = bb.y; h[6] = bb.z; h[7] = bb.w;
        ((int4*)hist)[2 * tid] = z4; ((int4*)hist)[2 * tid + 1] = z4;
    }
    int local = h[0]+h[1]+h[2]+h[3]+h[4]+h[5]+h[6]+h[7];
    int above = block_suffix_excl(local, tid, wtmp);
    if (above < k && above + local >= k) {
        int run = above;
        for (int j = 7; j >= 0; j--) {
            int c = h[j];
            if (run < k && run + c >= k) { sctl[0] = tid * 8 + j; sctl[1] = k - run; }
            run += c;
        }
    }
    __syncthreads();
    const uint32_t b = (uint32_t)sctl[0];
    const int need = sctl[1];

    // pass B: bits [20:10] within bin b
    for (int i = tid; i < W; i += NT) {
        uint32_t k2 = ckey[i];
        if ((k2 >> 21) == b) atomicAdd(&hist[(k2 >> 10) & 0x7FF], 1);
    }
    __syncthreads();
    {
        int4 a = ((int4*)hist)[2 * tid];
        int4 bb = ((int4*)hist)[2 * tid + 1];
        h[0] = a.x; h[1] = a.y; h[2] = a.z; h[3] = a.w;
        h[4] = bb.x; h[5] = bb.y; h[6] = bb.z; h[7] = bb.w;
        ((int4*)hist)[2 * tid] = z4; ((int4*)hist)[2 * tid + 1] = z4;
    }
    local = h[0]+h[1]+h[2]+h[3]+h[4]+h[5]+h[6]+h[7];
    above = block_suffix_excl(local, tid, wtmp);
    if (above < need && above + local >= need) {
        int run = above;
        for (int j = 7; j >= 0; j--) {
            int c = h[j];
            if (run < need && run + c >= need) { sctl[2] = tid * 8 + j; sctl[3] = need - run; }
            run += c;
        }
    }
    __syncthreads();
    const int need2 = sctl[3];
    const uint32_t pref22 = (b << 11) | (uint32_t)sctl[2];

    // pass C: bits [9:0]
    for (int i = tid; i < W; i += NT) {
        uint32_t k2 = ckey[i];
        if ((k2 >> 10) == pref22) atomicAdd(&hist[k2 & 0x3FF], 1);
    }
    __syncthreads();
    {
        int4 a = ((int4*)hist)[tid];
        int h4[4] = {a.x, a.y, a.z, a.w};
        ((int4*)hist)[tid] = z4;
        int l3 = h4[0]+h4[1]+h4[2]+h4[3];
        int ab3 = block_suffix_excl(l3, tid, wtmp);
        if (ab3 < need2 && ab3 + l3 >= need2) {
            int run = ab3;
            for (int j = 3; j >= 0; j--) {
                int c = h4[j];
                if (run < need2 && run + c >= need2) { sctl[0] = tid * 4 + j; sctl[1] = need2 - run; }
                run += c;
            }
        }
    }
    __syncthreads();
    Sel s;
    s.T = (pref22 << 10) | (uint32_t)sctl[0];
    s.need_eq = sctl[1];
    return s;
}

__global__ __launch_bounds__(NT, 6) void retention_kernel(
    const float* __restrict__ logits, float* __restrict__ out)
{
    __shared__ int      hist[2048];     // 8 KB, kept all-zero between passes
    __shared__ uint32_t ckey[CAP];      // 2 KB candidate keys
    __shared__ uint16_t cidx[CAP];      // 1 KB candidate class indices
    __shared__ uint32_t bitmap[NT];     // 1 KB selection bitmap
    __shared__ int      wtmp[8];
    __shared__ int      sctl[4];
    __shared__ int      s_above, sW;

    const int row  = blockIdx.x;
    const int tid  = threadIdx.x;
    const int4 z4  = make_int4(0, 0, 0, 0);

    ((int4*)hist)[2 * tid]     = z4;
    ((int4*)hist)[2 * tid + 1] = z4;
    bitmap[tid] = 0;
    if (tid == 0) { sW = 0; s_above = 0; }
    __syncthreads();

    // ---- Phase 0: single streaming pass. Prefilter-compact + count(logit>=0) ----
    const float4* in4 = (const float4*)(logits + (size_t)row * KC);
    int cnt0 = 0;
    #pragma unroll
    for (int i = 0; i < PER / 4; i++) {
        int v = tid + i * NT;
        float4 f = in4[v];
        uint4 kk;
        kk.x = fkey(__float_as_uint(f.x));
        kk.y = fkey(__float_as_uint(f.y));
        kk.z = fkey(__float_as_uint(f.z));
        kk.w = fkey(__float_as_uint(f.w));
        cnt0 += (kk.x >= 0x80000000u) + (kk.y >= 0x80000000u)
              + (kk.z >= 0x80000000u) + (kk.w >= 0x80000000u);
        #pragma unroll
        for (int c = 0; c < 4; c++) {
            uint32_t key = (c == 0) ? kk.x : (c == 1) ? kk.y : (c == 2) ? kk.z : kk.w;
            if (key >= KTHR) {                       // ~4% of elements
                int pos = atomicAdd(&sW, 1);
                if (pos < CAP) { ckey[pos] = key; cidx[pos] = (uint16_t)(v * 4 + c); }
            }
        }
    }
    cnt0 = __reduce_add_sync(0xFFFFFFFFu, cnt0);
    if ((tid & 31) == 0) atomicAdd(&s_above, cnt0);
    __syncthreads();

    const int ktrain = min(max(s_above, MINC), MAXC);
    int W = sW;
    uint32_t T;
    int need_eq;

    if (W <= CAP && W >= ktrain) {
        // ================= FAST PATH: select among prefiltered candidates =======
        Sel s = refine_T(ckey, W, ktrain, tid, hist, wtmp, sctl);
        T = s.T; need_eq = s.need_eq;

        for (int i = tid; i < W; i += NT) {
            uint32_t ki = ckey[i];
            int di = cidx[i];
            if (ki > T) {
                atomicOr(&bitmap[di >> 5], 1u << (di & 31));
            } else if (ki == T) {
                int rank = 0;                        // lowest-index equals win
                for (int j = 0; j < W; j++)
                    rank += (ckey[j] == T) & ((int)cidx[j] < di);
                if (rank < need_eq) atomicOr(&bitmap[di >> 5], 1u << (di & 31));
            }
        }
        __syncthreads();
    } else {
        // ================= SLOW PATH (prefilter miss — practically never) =======
        const float* in1 = (const float*)in4;
        // full 11-bit histogram from global
        for (int i = tid; i < KC; i += NT)
            atomicAdd(&hist[fkey(__float_as_uint(in1[i])) >> 21], 1);
        __syncthreads();
        int h[8];
        {
            int4 a = ((int4*)hist)[2 * tid];
            int4 bb = ((int4*)hist)[2 * tid + 1];
            h[0]=a.x;h[1]=a.y;h[2]=a.z;h[3]=a.w;h[4]=bb.x;h[5]=bb.y;h[6]=bb.z;h[7]=bb.w;
            ((int4*)hist)[2 * tid] = z4; ((int4*)hist)[2 * tid + 1] = z4;
        }
        int local = h[0]+h[1]+h[2]+h[3]+h[4]+h[5]+h[6]+h[7];
        int above = block_suffix_excl(local, tid, wtmp);
        if (above < ktrain && above + local >= ktrain) {
            int run = above;
            for (int j = 7; j >= 0; j--) {
                int c = h[j];
                if (run < ktrain && run + c >= ktrain) { sctl[0] = tid * 8 + j; sctl[1] = ktrain - run; }
                run += c;
            }
        }
        __syncthreads();
        const uint32_t b = (uint32_t)sctl[0];

        // compact candidates bin >= b from global
        if (tid == 0) sW = 0;
        __syncthreads();
        for (int i = tid; i < KC; i += NT) {
            uint32_t k2 = fkey(__float_as_uint(in1[i]));
            if ((k2 >> 21) >= b) {
                int pos = atomicAdd(&sW, 1);
                if (pos < CAP) { ckey[pos] = k2; cidx[pos] = (uint16_t)i; }
            }
        }
        __syncthreads();
        W = sW;

        if (W <= CAP) {
            Sel s = refine_T(ckey, W, ktrain, tid, hist, wtmp, sctl);
            T = s.T; need_eq = s.need_eq;
            for (int i = tid; i < W; i += NT) {
                uint32_t ki = ckey[i];
                int di = cidx[i];
                if (ki > T) {
                    atomicOr(&bitmap[di >> 5], 1u << (di & 31));
                } else if (ki == T) {
                    int rank = 0;
                    for (int j = 0; j < W; j++)
                        rank += (ckey[j] == T) & ((int)cidx[j] < di);
                    if (rank < need_eq) atomicOr(&bitmap[di >> 5], 1u << (di & 31));
                }
            }
            __syncthreads();
        } else {
            // ---- ULTRA fallback: full global refine (boundary bin overflow) ----
            const int need = sctl[1];
            for (int i = tid; i < KC; i += NT) {
                uint32_t k2 = fkey(__float_as_uint(in1[i]));
                if ((k2 >> 21) == b) atomicAdd(&hist[(k2 >> 10) & 0x7FF], 1);
            }
            __syncthreads();
            {
                int4 a = ((int4*)hist)[2 * tid];
                int4 bb = ((int4*)hist)[2 * tid + 1];
                h[0]=a.x;h[1]=a.y;h[2]=a.z;h[3]=a.w;h[4]=bb.x;h[5]=bb.y;h[6]=bb.z;h[7]=bb.w;
                ((int4*)hist)[2 * tid] = z4; ((int4*)hist)[2 * tid + 1] = z4;
            }
            local = h[0]+h[1]+h[2]+h[3]+h[4]+h[5]+h[6]+h[7];
            above = block_suffix_excl(local, tid, wtmp);
            if (above < need && above + local >= need) {
                int run = above;
                for (int j = 7; j >= 0; j--) {
                    int c = h[j];
                    if (run < need && run + c >= need) { sctl[2] = tid * 8 + j; sctl[3] = need - run; }
                    run += c;
                }
            }
            __syncthreads();
            const int need2 = sctl[3];
            const uint32_t pref22 = (b << 11) | (uint32_t)sctl[2];

            for (int i = tid; i < KC; i += NT) {
                uint32_t k2 = fkey(__float_as_uint(in1[i]));
                if ((k2 >> 10) == pref22) atomicAdd(&hist[k2 & 0x3FF], 1);
            }
            __syncthreads();
            {
                int4 a = ((int4*)hist)[tid];
                int h4[4] = {a.x, a.y, a.z, a.w};
                ((int4*)hist)[tid] = z4;
                int l3 = h4[0]+h4[1]+h4[2]+h4[3];
                int ab3 = block_suffix_excl(l3, tid, wtmp);
                if (ab3 < need2 && ab3 + l3 >= need2) {
                    int run = ab3;
                    for (int j = 3; j >= 0; j--) {
                        int c = h4[j];
                        if (run < need2 && run + c >= need2) { sctl[0] = tid * 4 + j; sctl[1] = need2 - run; }
                        run += c;
                    }
                }
            }
            __syncthreads();
            T = (pref22 << 10) | (uint32_t)sctl[0];
            need_eq = sctl[1];

            if (tid == 0) sW = 0;
            __syncthreads();
            for (int i = tid; i < KC; i += NT) {
                uint32_t k2 = fkey(__float_as_uint(in1[i]));
                if (k2 > T) atomicOr(&bitmap[i >> 5], 1u << (i & 31));
                else if (k2 == T) {
                    int pos = atomicAdd(&sW, 1);
                    if (pos < CAP) cidx[pos] = (uint16_t)i;
                }
            }
            __syncthreads();
            int We = min(sW, CAP);
            for (int i = tid; i < We; i += NT) {
                int di = cidx[i];
                int rank = 0;
                for (int j = 0; j < We; j++) rank += ((int)cidx[j] < di);
                if (rank < need_eq) atomicOr(&bitmap[di >> 5], 1u << (di & 31));
            }
            __syncthreads();
        }
    }

    // ---- Emission: bitmap popcount + block prefix scan + bit walk ----
    uint32_t wbits = bitmap[tid];
    int cnt = __popc(wbits);
    int pos = block_prefix_excl(cnt, tid, wtmp);

    float* __restrict__ bs_out  = out;
    float* __restrict__ cls_out = out + (size_t)BSZ * MAXC;
    float* __restrict__ msk_out = out + (size_t)2 * BSZ * MAXC;
    const size_t rbase = (size_t)row * MAXC;

    while (wbits) {
        int bit = __ffs(wbits) - 1;
        wbits &= wbits - 1;
        cls_out[rbase + pos] = (float)(tid * 32 + bit);
        pos++;
    }

    // ---- Padding / bs_idx / mask ----
    if (tid < MAXC) {
        bs_out[rbase + tid] = (tid < ktrain) ? (float)row : -1.0f;
        if (tid >= ktrain) cls_out[rbase + tid] = -1.0f;
        msk_out[rbase + tid] = (tid < ktrain) ? 1.0f : 0.0f;
    }
}

extern "C" void kernel_launch(void* const* d_in, const int* in_sizes, int n_in,
                              void* d_out, int out_size)
{
    const float* logits = (const float*)d_in[0];
    float* out = (float*)d_out;
    retention_kernel<<<BSZ, NT>>>(logits, out);
}

// round 12
// speedup vs baseline: 1.2280x; 1.2280x over previous
#include <cuda_runtime.h>
#include <stdint.h>

#define BSZ  16384
#define KC   8192
#define MAXC 100
#define MINC 20
#define NT   256
#define PER  32
#define CAP  512
#define KTHR 0x403FFFFFu   // fkey(-1.5f): prefilter threshold in key space

__device__ __forceinline__ uint32_t fkey(uint32_t u) {
    return u ^ (uint32_t)(((int)u >> 31) | (int)0x80000000);   // order-preserving
}

// sum over threads with tid' > tid (block exclusive suffix). 2 barriers.
__device__ __forceinline__ int block_suffix_excl(int v, int tid, volatile int* wtmp) {
    int lane = tid & 31, w = tid >> 5;
    int x = v;
    #pragma unroll
    for (int off = 1; off < 32; off <<= 1) {
        int t = __shfl_down_sync(0xFFFFFFFFu, x, off);
        if (lane + off < 32) x += t;
    }
    if (lane == 0) wtmp[w] = x;
    __syncthreads();
    int above = 0;
    #pragma unroll
    for (int j = 0; j < 8; j++) above += (j > w) ? wtmp[j] : 0;
    __syncthreads();
    return above + (x - v);
}

// sum over threads with tid' < tid (block exclusive prefix). 2 barriers.
__device__ __forceinline__ int block_prefix_excl(int v, int tid, volatile int* wtmp) {
    int lane = tid & 31, w = tid >> 5;
    int x = v;
    #pragma unroll
    for (int off = 1; off < 32; off <<= 1) {
        int t = __shfl_up_sync(0xFFFFFFFFu, x, off);
        if (lane >= off) x += t;
    }
    if (lane == 31) wtmp[w] = x;
    __syncthreads();
    int below = 0;
    #pragma unroll
    for (int j = 0; j < 8; j++) below += (j < w) ? wtmp[j] : 0;
    __syncthreads();
    return below + (x - v);
}

struct Sel { uint32_t T; int need_eq; };

// Select rank-k largest among W candidates in ckey[] via 3 histogram passes.
// hist[] must be all-zero on entry; leaves it all-zero on exit.
__device__ __forceinline__ Sel refine_T(
    const uint32_t* ckey, int W, int k, int tid,
    int* hist, volatile int* wtmp, int* sctl /* [4] */)
{
    const int4 z4 = make_int4(0, 0, 0, 0);
    for (int i = tid; i < W; i += NT) atomicAdd(&hist[ckey[i] >> 21], 1);
    __syncthreads();
    int h[8];
    {
        int4 a = ((int4*)hist)[2 * tid];
        int4 bb = ((int4*)hist)[2 * tid + 1];
        h[0] = a.x; h[1] = a.y; h[2] = a.z; h[3] = a.w;
        h[4] = bb.x; h[5] = bb.y; h[6] = bb.z; h[7] = bb.w;
        ((int4*)hist)[2 * tid] = z4; ((int4*)hist)[2 * tid + 1] = z4;
    }
    int local = h[0]+h[1]+h[2]+h[3]+h[4]+h[5]+h[6]+h[7];
    int above = block_suffix_excl(local, tid, wtmp);
    if (above < k && above + local >= k) {
        int run = above;
        for (int j = 7; j >= 0; j--) {
            int c = h[j];
            if (run < k && run + c >= k) { sctl[0] = tid * 8 + j; sctl[1] = k - run; }
            run += c;
        }
    }
    __syncthreads();
    const uint32_t b = (uint32_t)sctl[0];
    const int need = sctl[1];

    for (int i = tid; i < W; i += NT) {
        uint32_t k2 = ckey[i];
        if ((k2 >> 21) == b) atomicAdd(&hist[(k2 >> 10) & 0x7FF], 1);
    }
    __syncthreads();
    {
        int4 a = ((int4*)hist)[2 * tid];
        int4 bb = ((int4*)hist)[2 * tid + 1];
        h[0] = a.x; h[1] = a.y; h[2] = a.z; h[3] = a.w;
        h[4] = bb.x; h[5] = bb.y; h[6] = bb.z; h[7] = bb.w;
        ((int4*)hist)[2 * tid] = z4; ((int4*)hist)[2 * tid + 1] = z4;
    }
    local = h[0]+h[1]+h[2]+h[3]+h[4]+h[5]+h[6]+h[7];
    above = block_suffix_excl(local, tid, wtmp);
    if (above < need && above + local >= need) {
        int run = above;
        for (int j = 7; j >= 0; j--) {
            int c = h[j];
            if (run < need && run + c >= need) { sctl[2] = tid * 8 + j; sctl[3] = need - run; }
            run += c;
        }
    }
    __syncthreads();
    const int need2 = sctl[3];
    const uint32_t pref22 = (b << 11) | (uint32_t)sctl[2];

    for (int i = tid; i < W; i += NT) {
        uint32_t k2 = ckey[i];
        if ((k2 >> 10) == pref22) atomicAdd(&hist[k2 & 0x3FF], 1);
    }
    __syncthreads();
    {
        int4 a = ((int4*)hist)[tid];
        int h4[4] = {a.x, a.y, a.z, a.w};
        ((int4*)hist)[tid] = z4;
        int l3 = h4[0]+h4[1]+h4[2]+h4[3];
        int ab3 = block_suffix_excl(l3, tid, wtmp);
        if (ab3 < need2 && ab3 + l3 >= need2) {
            int run = ab3;
            for (int j = 3; j >= 0; j--) {
                int c = h4[j];
                if (run < need2 && run + c >= need2) { sctl[0] = tid * 4 + j; sctl[1] = need2 - run; }
                run += c;
            }
        }
    }
    __syncthreads();
    Sel s;
    s.T = (pref22 << 10) | (uint32_t)sctl[0];
    s.need_eq = sctl[1];
    return s;
}

__global__ __launch_bounds__(NT, 6) void retention_kernel(
    const float* __restrict__ logits, float* __restrict__ out)
{
    __shared__ int      hist[2048];     // 8 KB, kept all-zero between passes
    __shared__ uint32_t ckey[CAP];      // 2 KB candidate keys
    __shared__ uint16_t cidx[CAP];      // 1 KB candidate class indices
    __shared__ uint32_t bitmap[NT];     // 1 KB selection bitmap
    __shared__ int      wtmp[8];
    __shared__ int      sctl[4];
    __shared__ int      s_above, sW;

    const int row  = blockIdx.x;
    const int tid  = threadIdx.x;
    const int4 z4  = make_int4(0, 0, 0, 0);

    ((int4*)hist)[2 * tid]     = z4;
    ((int4*)hist)[2 * tid + 1] = z4;
    bitmap[tid] = 0;
    if (tid == 0) { sW = 0; s_above = 0; }
    __syncthreads();

    // ---- Phase 0: single streaming pass, one rare branch per uint4 ----
    const float4* in4 = (const float4*)(logits + (size_t)row * KC);
    int cnt0 = 0;
    #pragma unroll
    for (int i = 0; i < PER / 4; i++) {
        int v = tid + i * NT;
        float4 f = in4[v];
        uint4 kk;
        kk.x = fkey(__float_as_uint(f.x));
        kk.y = fkey(__float_as_uint(f.y));
        kk.z = fkey(__float_as_uint(f.z));
        kk.w = fkey(__float_as_uint(f.w));
        cnt0 += (kk.x >> 31) + (kk.y >> 31) + (kk.z >> 31) + (kk.w >> 31);
        uint32_t hmask = (kk.x >= KTHR ? 1u : 0u) | (kk.y >= KTHR ? 2u : 0u)
                       | (kk.z >= KTHR ? 4u : 0u) | (kk.w >= KTHR ? 8u : 0u);
        if (hmask) {                                 // ~4.6% of uint4s
            #pragma unroll
            for (int c = 0; c < 4; c++) {
                if (hmask & (1u << c)) {
                    uint32_t key = (c == 0) ? kk.x : (c == 1) ? kk.y : (c == 2) ? kk.z : kk.w;
                    int pos = atomicAdd(&sW, 1);
                    if (pos < CAP) { ckey[pos] = key; cidx[pos] = (uint16_t)(v * 4 + c); }
                }
            }
        }
    }
    cnt0 = __reduce_add_sync(0xFFFFFFFFu, cnt0);
    if ((tid & 31) == 0) atomicAdd(&s_above, cnt0);
    __syncthreads();

    const int ktrain = min(max(s_above, MINC), MAXC);
    int W = sW;
    uint32_t T;
    int need_eq;

    if (W <= CAP && W >= ktrain) {
        // ================= FAST PATH: select among ~100 prefiltered candidates ====
        Sel s = refine_T(ckey, W, ktrain, tid, hist, wtmp, sctl);
        T = s.T; need_eq = s.need_eq;

        for (int i = tid; i < W; i += NT) {
            uint32_t ki = ckey[i];
            int di = cidx[i];
            if (ki > T) {
                atomicOr(&bitmap[di >> 5], 1u << (di & 31));
            } else if (ki == T) {
                int rank = 0;                        // lowest-index equals win
                for (int j = 0; j < W; j++)
                    rank += (ckey[j] == T) & ((int)cidx[j] < di);
                if (rank < need_eq) atomicOr(&bitmap[di >> 5], 1u << (di & 31));
            }
        }
        __syncthreads();
    } else {
        // ================= SLOW PATH (prefilter miss — ~never): exact from global ==
        const float* in1 = (const float*)in4;
        for (int i = tid; i < KC; i += NT)
            atomicAdd(&hist[fkey(__float_as_uint(in1[i])) >> 21], 1);
        __syncthreads();
        int h[8];
        {
            int4 a = ((int4*)hist)[2 * tid];
            int4 bb = ((int4*)hist)[2 * tid + 1];
            h[0]=a.x;h[1]=a.y;h[2]=a.z;h[3]=a.w;h[4]=bb.x;h[5]=bb.y;h[6]=bb.z;h[7]=bb.w;
            ((int4*)hist)[2 * tid] = z4; ((int4*)hist)[2 * tid + 1] = z4;
        }
        int local = h[0]+h[1]+h[2]+h[3]+h[4]+h[5]+h[6]+h[7];
        int above = block_suffix_excl(local, tid, wtmp);
        if (above < ktrain && above + local >= ktrain) {
            int run = above;
            for (int j = 7; j >= 0; j--) {
                int c = h[j];
                if (run < ktrain && run + c >= ktrain) { sctl[0] = tid * 8 + j; sctl[1] = ktrain - run; }
                run += c;
            }
        }
        __syncthreads();
        const uint32_t b = (uint32_t)sctl[0];

        if (tid == 0) sW = 0;
        __syncthreads();
        for (int i = tid; i < KC; i += NT) {
            uint32_t k2 = fkey(__float_as_uint(in1[i]));
            if ((k2 >> 21) >= b) {
                int pos = atomicAdd(&sW, 1);
                if (pos < CAP) { ckey[pos] = k2; cidx[pos] = (uint16_t)i; }
            }
        }
        __syncthreads();
        W = sW;

        if (W <= CAP) {
            Sel s = refine_T(ckey, W, ktrain, tid, hist, wtmp, sctl);
            T = s.T; need_eq = s.need_eq;
            for (int i = tid; i < W; i += NT) {
                uint32_t ki = ckey[i];
                int di = cidx[i];
                if (ki > T) {
                    atomicOr(&bitmap[di >> 5], 1u << (di & 31));
                } else if (ki == T) {
                    int rank = 0;
                    for (int j = 0; j < W; j++)
                        rank += (ckey[j] == T) & ((int)cidx[j] < di);
                    if (rank < need_eq) atomicOr(&bitmap[di >> 5], 1u << (di & 31));
                }
            }
            __syncthreads();
        } else {
            // ---- ULTRA fallback: full global refine (boundary bin overflow) ----
            const int need = sctl[1];
            for (int i = tid; i < KC; i += NT) {
                uint32_t k2 = fkey(__float_as_uint(in1[i]));
                if ((k2 >> 21) == b) atomicAdd(&hist[(k2 >> 10) & 0x7FF], 1);
            }
            __syncthreads();
            {
                int4 a = ((int4*)hist)[2 * tid];
                int4 bb = ((int4*)hist)[2 * tid + 1];
                h[0]=a.x;h[1]=a.y;h[2]=a.z;h[3]=a.w;h[4]=bb.x;h[5]=bb.y;h[6]=bb.z;h[7]=bb.w;
                ((int4*)hist)[2 * tid] = z4; ((int4*)hist)[2 * tid + 1] = z4;
            }
            local = h[0]+h[1]+h[2]+h[3]+h[4]+h[5]+h[6]+h[7];
            above = block_suffix_excl(local, tid, wtmp);
            if (above < need && above + local >= need) {
                int run = above;
                for (int j = 7; j >= 0; j--) {
                    int c = h[j];
                    if (run < need && run + c >= need) { sctl[2] = tid * 8 + j; sctl[3] = need - run; }
                    run += c;
                }
            }
            __syncthreads();
            const int need2 = sctl[3];
            const uint32_t pref22 = (b << 11) | (uint32_t)sctl[2];

            for (int i = tid; i < KC; i += NT) {
                uint32_t k2 = fkey(__float_as_uint(in1[i]));
                if ((k2 >> 10) == pref22) atomicAdd(&hist[k2 & 0x3FF], 1);
            }
            __syncthreads();
            {
                int4 a = ((int4*)hist)[tid];
                int h4[4] = {a.x, a.y, a.z, a.w};
                ((int4*)hist)[tid] = z4;
                int l3 = h4[0]+h4[1]+h4[2]+h4[3];
                int ab3 = block_suffix_excl(l3, tid, wtmp);
                if (ab3 < need2 && ab3 + l3 >= need2) {
                    int run = ab3;
                    for (int j = 3; j >= 0; j--) {
                        int c = h4[j];
                        if (run < need2 && run + c >= need2) { sctl[0] = tid * 4 + j; sctl[1] = need2 - run; }
                        run += c;
                    }
                }
            }
            __syncthreads();
            T = (pref22 << 10) | (uint32_t)sctl[0];
            need_eq = sctl[1];

            if (tid == 0) sW = 0;
            __syncthreads();
            for (int i = tid; i < KC; i += NT) {
                uint32_t k2 = fkey(__float_as_uint(in1[i]));
                if (k2 > T) atomicOr(&bitmap[i >> 5], 1u << (i & 31));
                else if (k2 == T) {
                    int pos = atomicAdd(&sW, 1);
                    if (pos < CAP) cidx[pos] = (uint16_t)i;
                }
            }
            __syncthreads();
            int We = min(sW, CAP);
            for (int i = tid; i < We; i += NT) {
                int di = cidx[i];
                int rank = 0;
                for (int j = 0; j < We; j++) rank += ((int)cidx[j] < di);
                if (rank < need_eq) atomicOr(&bitmap[di >> 5], 1u << (di & 31));
            }
            __syncthreads();
        }
    }

    // ---- Emission: bitmap popcount + block prefix scan + bit walk ----
    uint32_t wbits = bitmap[tid];
    int cnt = __popc(wbits);
    int pos = block_prefix_excl(cnt, tid, wtmp);

    float* __restrict__ bs_out  = out;
    float* __restrict__ cls_out = out + (size_t)BSZ * MAXC;
    float* __restrict__ msk_out = out + (size_t)2 * BSZ * MAXC;
    const size_t rbase = (size_t)row * MAXC;

    while (wbits) {
        int bit = __ffs(wbits) - 1;
        wbits &= wbits - 1;
        cls_out[rbase + pos] = (float)(tid * 32 + bit);
        pos++;
    }

    // ---- Padding / bs_idx / mask ----
    if (tid < MAXC) {
        bs_out[rbase + tid] = (tid < ktrain) ? (float)row : -1.0f;
        if (tid >= ktrain) cls_out[rbase + tid] = -1.0f;
        msk_out[rbase + tid] = (tid < ktrain) ? 1.0f : 0.0f;
    }
}

extern "C" void kernel_launch(void* const* d_in, const int* in_sizes, int n_in,
                              void* d_out, int out_size)
{
    const float* logits = (const float*)d_in[0];
    float* out = (float*)d_out;
    retention_kernel<<<BSZ, NT>>>(logits, out);
}

// round 13
// speedup vs baseline: 1.2402x; 1.0099x over previous
#include <cuda_runtime.h>
#include <stdint.h>

#define BSZ  16384
#define KC   8192
#define MAXC 100
#define MINC 20
#define NT   256
#define PER  32
#define CAP  512
#define HTHR 0xBFC00000u   // raw bits of -1.5f:  f >= -1.5  <=>  u <= HTHR
#define ZTHR 0x80000000u   // f >= 0.0 (incl -0.0)  <=>  u <= ZTHR

__device__ __forceinline__ uint32_t fkey(uint32_t u) {
    return u ^ (uint32_t)(((int)u >> 31) | (int)0x80000000);   // order-preserving
}

// sum over threads with tid' > tid (block exclusive suffix). 2 barriers.
__device__ __forceinline__ int block_suffix_excl(int v, int tid, volatile int* wtmp) {
    int lane = tid & 31, w = tid >> 5;
    int x = v;
    #pragma unroll
    for (int off = 1; off < 32; off <<= 1) {
        int t = __shfl_down_sync(0xFFFFFFFFu, x, off);
        if (lane + off < 32) x += t;
    }
    if (lane == 0) wtmp[w] = x;
    __syncthreads();
    int above = 0;
    #pragma unroll
    for (int j = 0; j < 8; j++) above += (j > w) ? wtmp[j] : 0;
    __syncthreads();
    return above + (x - v);
}

// sum over threads with tid' < tid (block exclusive prefix). 2 barriers.
__device__ __forceinline__ int block_prefix_excl(int v, int tid, volatile int* wtmp) {
    int lane = tid & 31, w = tid >> 5;
    int x = v;
    #pragma unroll
    for (int off = 1; off < 32; off <<= 1) {
        int t = __shfl_up_sync(0xFFFFFFFFu, x, off);
        if (lane >= off) x += t;
    }
    if (lane == 31) wtmp[w] = x;
    __syncthreads();
    int below = 0;
    #pragma unroll
    for (int j = 0; j < 8; j++) below += (j < w) ? wtmp[j] : 0;
    __syncthreads();
    return below + (x - v);
}

struct Sel { uint32_t T; int need_eq; };

// Select rank-k largest among W candidates in ckey[] via 3 histogram passes.
// hist[] must be all-zero on entry; leaves it all-zero on exit.
__device__ __forceinline__ Sel refine_T(
    const uint32_t* ckey, int W, int k, int tid,
    int* hist, volatile int* wtmp, int* sctl /* [4] */)
{
    const int4 z4 = make_int4(0, 0, 0, 0);
    for (int i = tid; i < W; i += NT) atomicAdd(&hist[ckey[i] >> 21], 1);
    __syncthreads();
    int h[8];
    {
        int4 a = ((int4*)hist)[2 * tid];
        int4 bb = ((int4*)hist)[2 * tid + 1];
        h[0] = a.x; h[1] = a.y; h[2] = a.z; h[3] = a.w;
        h[4] = bb.x; h[5] = bb.y; h[6] = bb.z; h[7] = bb.w;
        ((int4*)hist)[2 * tid] = z4; ((int4*)hist)[2 * tid + 1] = z4;
    }
    int local = h[0]+h[1]+h[2]+h[3]+h[4]+h[5]+h[6]+h[7];
    int above = block_suffix_excl(local, tid, wtmp);
    if (above < k && above + local >= k) {
        int run = above;
        for (int j = 7; j >= 0; j--) {
            int c = h[j];
            if (run < k && run + c >= k) { sctl[0] = tid * 8 + j; sctl[1] = k - run; }
            run += c;
        }
    }
    __syncthreads();
    const uint32_t b = (uint32_t)sctl[0];
    const int need = sctl[1];

    for (int i = tid; i < W; i += NT) {
        uint32_t k2 = ckey[i];
        if ((k2 >> 21) == b) atomicAdd(&hist[(k2 >> 10) & 0x7FF], 1);
    }
    __syncthreads();
    {
        int4 a = ((int4*)hist)[2 * tid];
        int4 bb = ((int4*)hist)[2 * tid + 1];
        h[0] = a.x; h[1] = a.y; h[2] = a.z; h[3] = a.w;
        h[4] = bb.x; h[5] = bb.y; h[6] = bb.z; h[7] = bb.w;
        ((int4*)hist)[2 * tid] = z4; ((int4*)hist)[2 * tid + 1] = z4;
    }
    local = h[0]+h[1]+h[2]+h[3]+h[4]+h[5]+h[6]+h[7];
    above = block_suffix_excl(local, tid, wtmp);
    if (above < need && above + local >= need) {
        int run = above;
        for (int j = 7; j >= 0; j--) {
            int c = h[j];
            if (run < need && run + c >= need) { sctl[2] = tid * 8 + j; sctl[3] = need - run; }
            run += c;
        }
    }
    __syncthreads();
    const int need2 = sctl[3];
    const uint32_t pref22 = (b << 11) | (uint32_t)sctl[2];

    for (int i = tid; i < W; i += NT) {
        uint32_t k2 = ckey[i];
        if ((k2 >> 10) == pref22) atomicAdd(&hist[k2 & 0x3FF], 1);
    }
    __syncthreads();
    {
        int4 a = ((int4*)hist)[tid];
        int h4[4] = {a.x, a.y, a.z, a.w};
        ((int4*)hist)[tid] = z4;
        int l3 = h4[0]+h4[1]+h4[2]+h4[3];
        int ab3 = block_suffix_excl(l3, tid, wtmp);
        if (ab3 < need2 && ab3 + l3 >= need2) {
            int run = ab3;
            for (int j = 3; j >= 0; j--) {
                int c = h4[j];
                if (run < need2 && run + c >= need2) { sctl[0] = tid * 4 + j; sctl[1] = need2 - run; }
                run += c;
            }
        }
    }
    __syncthreads();
    Sel s;
    s.T = (pref22 << 10) | (uint32_t)sctl[0];
    s.need_eq = sctl[1];
    return s;
}

__global__ __launch_bounds__(NT, 6) void retention_kernel(
    const float* __restrict__ logits, float* __restrict__ out)
{
    __shared__ int      hist[2048];     // 8 KB, kept all-zero between passes
    __shared__ uint32_t ckey[CAP];      // 2 KB candidate keys
    __shared__ uint16_t cidx[CAP];      // 1 KB candidate class indices
    __shared__ uint32_t bitmap[NT];     // 1 KB selection bitmap
    __shared__ int      wtmp[8];
    __shared__ int      sctl[4];
    __shared__ int      s_above, sW;

    const int row  = blockIdx.x;
    const int tid  = threadIdx.x;
    const int4 z4  = make_int4(0, 0, 0, 0);

    ((int4*)hist)[2 * tid]     = z4;
    ((int4*)hist)[2 * tid + 1] = z4;
    bitmap[tid] = 0;
    if (tid == 0) { sW = 0; s_above = 0; }
    __syncthreads();

    // ---- Phase 0: stream raw bits. 2 unsigned compares per element. ----
    const uint4* in4 = (const uint4*)(logits + (size_t)row * KC);
    int cnt0 = 0;
    #pragma unroll
    for (int i = 0; i < PER / 4; i++) {
        int v = tid + i * NT;
        uint4 u = in4[v];
        cnt0 += (u.x <= ZTHR) + (u.y <= ZTHR) + (u.z <= ZTHR) + (u.w <= ZTHR);
        uint32_t hmask = (u.x <= HTHR ? 1u : 0u) | (u.y <= HTHR ? 2u : 0u)
                       | (u.z <= HTHR ? 4u : 0u) | (u.w <= HTHR ? 8u : 0u);
        if (hmask) {                                 // ~4.6% of uint4s
            #pragma unroll
            for (int c = 0; c < 4; c++) {
                if (hmask & (1u << c)) {
                    uint32_t raw = (c == 0) ? u.x : (c == 1) ? u.y : (c == 2) ? u.z : u.w;
                    int pos = atomicAdd(&sW, 1);
                    if (pos < CAP) { ckey[pos] = fkey(raw); cidx[pos] = (uint16_t)(v * 4 + c); }
                }
            }
        }
    }
    cnt0 = __reduce_add_sync(0xFFFFFFFFu, cnt0);
    if ((tid & 31) == 0) atomicAdd(&s_above, cnt0);
    __syncthreads();

    const int ktrain = min(max(s_above, MINC), MAXC);
    int W = sW;
    uint32_t T;
    int need_eq;

    if (W <= CAP && W >= ktrain) {
        // ================= FAST PATH: select among ~100 prefiltered candidates ====
        Sel s = refine_T(ckey, W, ktrain, tid, hist, wtmp, sctl);
        T = s.T; need_eq = s.need_eq;

        for (int i = tid; i < W; i += NT) {
            uint32_t ki = ckey[i];
            int di = cidx[i];
            if (ki > T) {
                atomicOr(&bitmap[di >> 5], 1u << (di & 31));
            } else if (ki == T) {
                int rank = 0;                        // lowest-index equals win
                for (int j = 0; j < W; j++)
                    rank += (ckey[j] == T) & ((int)cidx[j] < di);
                if (rank < need_eq) atomicOr(&bitmap[di >> 5], 1u << (di & 31));
            }
        }
        __syncthreads();
    } else {
        // ================= SLOW PATH (prefilter miss — ~never): exact from global ==
        const float* in1 = (const float*)in4;
        for (int i = tid; i < KC; i += NT)
            atomicAdd(&hist[fkey(__float_as_uint(in1[i])) >> 21], 1);
        __syncthreads();
        int h[8];
        {
            int4 a = ((int4*)hist)[2 * tid];
            int4 bb = ((int4*)hist)[2 * tid + 1];
            h[0]=a.x;h[1]=a.y;h[2]=a.z;h[3]=a.w;h[4]=bb.x;h[5]=bb.y;h[6]=bb.z;h[7]=bb.w;
            ((int4*)hist)[2 * tid] = z4; ((int4*)hist)[2 * tid + 1] = z4;
        }
        int local = h[0]+h[1]+h[2]+h[3]+h[4]+h[5]+h[6]+h[7];
        int above = block_suffix_excl(local, tid, wtmp);
        if (above < ktrain && above + local >= ktrain) {
            int run = above;
            for (int j = 7; j >= 0; j--) {
                int c = h[j];
                if (run < ktrain && run + c >= ktrain) { sctl[0] = tid * 8 + j; sctl[1] = ktrain - run; }
                run += c;
            }
        }
        __syncthreads();
        const uint32_t b = (uint32_t)sctl[0];

        if (tid == 0) sW = 0;
        __syncthreads();
        for (int i = tid; i < KC; i += NT) {
            uint32_t k2 = fkey(__float_as_uint(in1[i]));
            if ((k2 >> 21) >= b) {
                int pos = atomicAdd(&sW, 1);
                if (pos < CAP) { ckey[pos] = k2; cidx[pos] = (uint16_t)i; }
            }
        }
        __syncthreads();
        W = sW;

        if (W <= CAP) {
            Sel s = refine_T(ckey, W, ktrain, tid, hist, wtmp, sctl);
            T = s.T; need_eq = s.need_eq;
            for (int i = tid; i < W; i += NT) {
                uint32_t ki = ckey[i];
                int di = cidx[i];
                if (ki > T) {
                    atomicOr(&bitmap[di >> 5], 1u << (di & 31));
                } else if (ki == T) {
                    int rank = 0;
                    for (int j = 0; j < W; j++)
                        rank += (ckey[j] == T) & ((int)cidx[j] < di);
                    if (rank < need_eq) atomicOr(&bitmap[di >> 5], 1u << (di & 31));
                }
            }
            __syncthreads();
        } else {
            // ---- ULTRA fallback: full global refine (boundary bin overflow) ----
            const int need = sctl[1];
            for (int i = tid; i < KC; i += NT) {
                uint32_t k2 = fkey(__float_as_uint(in1[i]));
                if ((k2 >> 21) == b) atomicAdd(&hist[(k2 >> 10) & 0x7FF], 1);
            }
            __syncthreads();
            {
                int4 a = ((int4*)hist)[2 * tid];
                int4 bb = ((int4*)hist)[2 * tid + 1];
                h[0]=a.x;h[1]=a.y;h[2]=a.z;h[3]=a.w;h[4]=bb.x;h[5]=bb.y;h[6]=bb.z;h[7]=bb.w;
                ((int4*)hist)[2 * tid] = z4; ((int4*)hist)[2 * tid + 1] = z4;
            }
            local = h[0]+h[1]+h[2]+h[3]+h[4]+h[5]+h[6]+h[7];
            above = block_suffix_excl(local, tid, wtmp);
            if (above < need && above + local >= need) {
                int run = above;
                for (int j = 7; j >= 0; j--) {
                    int c = h[j];
                    if (run < need && run + c >= need) { sctl[2] = tid * 8 + j; sctl[3] = need - run; }
                    run += c;
                }
            }
            __syncthreads();
            const int need2 = sctl[3];
            const uint32_t pref22 = (b << 11) | (uint32_t)sctl[2];

            for (int i = tid; i < KC; i += NT) {
                uint32_t k2 = fkey(__float_as_uint(in1[i]));
                if ((k2 >> 10) == pref22) atomicAdd(&hist[k2 & 0x3FF], 1);
            }
            __syncthreads();
            {
                int4 a = ((int4*)hist)[tid];
                int h4[4] = {a.x, a.y, a.z, a.w};
                ((int4*)hist)[tid] = z4;
                int l3 = h4[0]+h4[1]+h4[2]+h4[3];
                int ab3 = block_suffix_excl(l3, tid, wtmp);
                if (ab3 < need2 && ab3 + l3 >= need2) {
                    int run = ab3;
                    for (int j = 3; j >= 0; j--) {
                        int c = h4[j];
                        if (run < need2 && run + c >= need2) { sctl[0] = tid * 4 + j; sctl[1] = need2 - run; }
                        run += c;
                    }
                }
            }
            __syncthreads();
            T = (pref22 << 10) | (uint32_t)sctl[0];
            need_eq = sctl[1];

            if (tid == 0) sW = 0;
            __syncthreads();
            for (int i = tid; i < KC; i += NT) {
                uint32_t k2 = fkey(__float_as_uint(in1[i]));
                if (k2 > T) atomicOr(&bitmap[i >> 5], 1u << (i & 31));
                else if (k2 == T) {
                    int pos = atomicAdd(&sW, 1);
                    if (pos < CAP) cidx[pos] = (uint16_t)i;
                }
            }
            __syncthreads();
            int We = min(sW, CAP);
            for (int i = tid; i < We; i += NT) {
                int di = cidx[i];
                int rank = 0;
                for (int j = 0; j < We; j++) rank += ((int)cidx[j] < di);
                if (rank < need_eq) atomicOr(&bitmap[di >> 5], 1u << (di & 31));
            }
            __syncthreads();
        }
    }

    // ---- Emission: bitmap popcount + block prefix scan + bit walk ----
    uint32_t wbits = bitmap[tid];
    int cnt = __popc(wbits);
    int pos = block_prefix_excl(cnt, tid, wtmp);

    float* __restrict__ bs_out  = out;
    float* __restrict__ cls_out = out + (size_t)BSZ * MAXC;
    float* __restrict__ msk_out = out + (size_t)2 * BSZ * MAXC;
    const size_t rbase = (size_t)row * MAXC;

    while (wbits) {
        int bit = __ffs(wbits) - 1;
        wbits &= wbits - 1;
        cls_out[rbase + pos] = (float)(tid * 32 + bit);
        pos++;
    }

    // ---- Padding / bs_idx / mask ----
    if (tid < MAXC) {
        bs_out[rbase + tid] = (tid < ktrain) ? (float)row : -1.0f;
        if (tid >= ktrain) cls_out[rbase + tid] = -1.0f;
        msk_out[rbase + tid] = (tid < ktrain) ? 1.0f : 0.0f;
    }
}

extern "C" void kernel_launch(void* const* d_in, const int* in_sizes, int n_in,
                              void* d_out, int out_size)
{
    const float* logits = (const float*)d_in[0];
    float* out = (float*)d_out;
    retention_kernel<<<BSZ, NT>>>(logits, out);
}

// round 15
// speedup vs baseline: 2.0670x; 1.6667x over previous
#include <cuda_runtime.h>
#include <stdint.h>

#define BSZ  16384
#define KC   8192
#define MAXC 100
#define MINC 20
#define NT   256
#define PER  32
#define CAP  512
#define HTHR 0xBFC00000u   // raw bits of -1.5f:  f >= -1.5  <=>  u <= HTHR
#define ZTHR 0x80000000u   // f >= 0.0 (incl -0.0)  <=>  u <= ZTHR

__device__ __forceinline__ uint32_t fkey(uint32_t u) {
    return u ^ (uint32_t)(((int)u >> 31) | (int)0x80000000);   // order-preserving
}

// sum over threads with tid' > tid (block exclusive suffix). 2 barriers.
__device__ __forceinline__ int block_suffix_excl(int v, int tid, volatile int* wtmp) {
    int lane = tid & 31, w = tid >> 5;
    int x = v;
    #pragma unroll
    for (int off = 1; off < 32; off <<= 1) {
        int t = __shfl_down_sync(0xFFFFFFFFu, x, off);
        if (lane + off < 32) x += t;
    }
    if (lane == 0) wtmp[w] = x;
    __syncthreads();
    int above = 0;
    #pragma unroll
    for (int j = 0; j < 8; j++) above += (j > w) ? wtmp[j] : 0;
    __syncthreads();
    return above + (x - v);
}

// sum over threads with tid' < tid (block exclusive prefix). 2 barriers.
__device__ __forceinline__ int block_prefix_excl(int v, int tid, volatile int* wtmp) {
    int lane = tid & 31, w = tid >> 5;
    int x = v;
    #pragma unroll
    for (int off = 1; off < 32; off <<= 1) {
        int t = __shfl_up_sync(0xFFFFFFFFu, x, off);
        if (lane >= off) x += t;
    }
    if (lane == 31) wtmp[w] = x;
    __syncthreads();
    int below = 0;
    #pragma unroll
    for (int j = 0; j < 8; j++) below += (j < w) ? wtmp[j] : 0;
    __syncthreads();
    return below + (x - v);
}

__global__ __launch_bounds__(NT, 5) void retention_kernel(
    const float* __restrict__ logits, float* __restrict__ out)
{
    __shared__ uint64_t cc[CAP];        // 4 KB: (key<<16) | (8191-idx)
    __shared__ uint32_t bitmap[NT];     // 1 KB selection bitmap
    __shared__ int      hist[2048];     // 8 KB (slow path only)
    __shared__ int      wtmp[8];
    __shared__ int      sctl[4];
    __shared__ int      s_above, sW;

    const int row  = blockIdx.x;
    const int tid  = threadIdx.x;

    bitmap[tid] = 0;
    if (tid == 0) { sW = 0; s_above = 0; }
    __syncthreads();

    // ---- Phase 0: stream raw bits, 4-deep batched loads (MLP), rare compact ----
    const uint4* in4 = (const uint4*)(logits + (size_t)row * KC);
    int cnt0 = 0;
    #pragma unroll
    for (int half = 0; half < 2; half++) {
        uint4 u[4];
        #pragma unroll
        for (int i = 0; i < 4; i++) u[i] = in4[tid + (half * 4 + i) * NT];
        #pragma unroll
        for (int i = 0; i < 4; i++) {
            int v = tid + (half * 4 + i) * NT;
            cnt0 += (u[i].x <= ZTHR) + (u[i].y <= ZTHR) + (u[i].z <= ZTHR) + (u[i].w <= ZTHR);
            uint32_t hm = (u[i].x <= HTHR ? 1u : 0u) | (u[i].y <= HTHR ? 2u : 0u)
                        | (u[i].z <= HTHR ? 4u : 0u) | (u[i].w <= HTHR ? 8u : 0u);
            if (hm) {                                    // ~4.6% of uint4s
                #pragma unroll
                for (int c = 0; c < 4; c++) {
                    if (hm & (1u << c)) {
                        uint32_t raw = (c == 0) ? u[i].x : (c == 1) ? u[i].y : (c == 2) ? u[i].z : u[i].w;
                        int pos = atomicAdd(&sW, 1);
                        if (pos < CAP)
                            cc[pos] = ((uint64_t)fkey(raw) << 16) | (uint32_t)(8191 - (v * 4 + c));
                    }
                }
            }
        }
    }
    cnt0 = __reduce_add_sync(0xFFFFFFFFu, cnt0);
    if ((tid & 31) == 0) atomicAdd(&s_above, cnt0);
    __syncthreads();

    const int ktrain = min(max(s_above, MINC), MAXC);
    int W = sW;
    bool done = false;

    if (W <= CAP && W >= ktrain) {
        // ======== FAST PATH: exact top-k by pairwise rank (no barriers) =========
        for (int i = tid; i < W; i += NT) {
            uint64_t ci = cc[i];
            int rank = 0;
            #pragma unroll 4
            for (int j = 0; j < W; j++) rank += (cc[j] > ci);   // broadcast LDS.64
            if (rank < ktrain) {
                int di = 8191 - (int)(ci & 0xFFFFu);
                atomicOr(&bitmap[di >> 5], 1u << (di & 31));
            }
        }
        __syncthreads();
        done = true;
    }

    if (!done) {
        // ======== SLOW PATH (prefilter miss — ~never): exact from global ========
        const float* in1 = (const float*)in4;
        const int4 z4 = make_int4(0, 0, 0, 0);
        ((int4*)hist)[2 * tid] = z4; ((int4*)hist)[2 * tid + 1] = z4;
        __syncthreads();
        for (int i = tid; i < KC; i += NT)
            atomicAdd(&hist[fkey(__float_as_uint(in1[i])) >> 21], 1);
        __syncthreads();
        int h[8];
        {
            int4 a = ((int4*)hist)[2 * tid];
            int4 bb = ((int4*)hist)[2 * tid + 1];
            h[0]=a.x;h[1]=a.y;h[2]=a.z;h[3]=a.w;h[4]=bb.x;h[5]=bb.y;h[6]=bb.z;h[7]=bb.w;
            ((int4*)hist)[2 * tid] = z4; ((int4*)hist)[2 * tid + 1] = z4;
        }
        int local = h[0]+h[1]+h[2]+h[3]+h[4]+h[5]+h[6]+h[7];
        int above = block_suffix_excl(local, tid, wtmp);
        if (above < ktrain && above + local >= ktrain) {
            int run = above;
            for (int j = 7; j >= 0; j--) {
                int c = h[j];
                if (run < ktrain && run + c >= ktrain) { sctl[0] = tid * 8 + j; sctl[1] = ktrain - run; }
                run += c;
            }
        }
        __syncthreads();
        const uint32_t b = (uint32_t)sctl[0];

        if (tid == 0) sW = 0;
        __syncthreads();
        for (int i = tid; i < KC; i += NT) {
            uint32_t k2 = fkey(__float_as_uint(in1[i]));
            if ((k2 >> 21) >= b) {
                int pos = atomicAdd(&sW, 1);
                if (pos < CAP) cc[pos] = ((uint64_t)k2 << 16) | (uint32_t)(8191 - i);
            }
        }
        __syncthreads();
        W = sW;

        if (W <= CAP) {
            for (int i = tid; i < W; i += NT) {
                uint64_t ci = cc[i];
                int rank = 0;
                for (int j = 0; j < W; j++) rank += (cc[j] > ci);
                if (rank < ktrain) {
                    int di = 8191 - (int)(ci & 0xFFFFu);
                    atomicOr(&bitmap[di >> 5], 1u << (di & 31));
                }
            }
            __syncthreads();
        } else {
            // ---- ULTRA fallback: histogram refine to exact threshold ----
            const int need = sctl[1];
            for (int i = tid; i < KC; i += NT) {
                uint32_t k2 = fkey(__float_as_uint(in1[i]));
                if ((k2 >> 21) == b) atomicAdd(&hist[(k2 >> 10) & 0x7FF], 1);
            }
            __syncthreads();
            {
                int4 a = ((int4*)hist)[2 * tid];
                int4 bb = ((int4*)hist)[2 * tid + 1];
                h[0]=a.x;h[1]=a.y;h[2]=a.z;h[3]=a.w;h[4]=bb.x;h[5]=bb.y;h[6]=bb.z;h[7]=bb.w;
                ((int4*)hist)[2 * tid] = z4; ((int4*)hist)[2 * tid + 1] = z4;
            }
            local = h[0]+h[1]+h[2]+h[3]+h[4]+h[5]+h[6]+h[7];
            above = block_suffix_excl(local, tid, wtmp);
            if (above < need && above + local >= need) {
                int run = above;
                for (int j = 7; j >= 0; j--) {
                    int c = h[j];
                    if (run < need && run + c >= need) { sctl[2] = tid * 8 + j; sctl[3] = need - run; }
                    run += c;
                }
            }
            __syncthreads();
            const int need2 = sctl[3];
            const uint32_t pref22 = (b << 11) | (uint32_t)sctl[2];

            for (int i = tid; i < KC; i += NT) {
                uint32_t k2 = fkey(__float_as_uint(in1[i]));
                if ((k2 >> 10) == pref22) atomicAdd(&hist[k2 & 0x3FF], 1);
            }
            __syncthreads();
            {
                int4 a = ((int4*)hist)[tid];
                int h4[4] = {a.x, a.y, a.z, a.w};
                ((int4*)hist)[tid] = z4;
                int l3 = h4[0]+h4[1]+h4[2]+h4[3];
                int ab3 = block_suffix_excl(l3, tid, wtmp);
                if (ab3 < need2 && ab3 + l3 >= need2) {
                    int run = ab3;
                    for (int j = 3; j >= 0; j--) {
                        int c = h4[j];
                        if (run < need2 && run + c >= need2) { sctl[0] = tid * 4 + j; sctl[1] = need2 - run; }
                        run += c;
                    }
                }
            }
            __syncthreads();
            const uint32_t T = (pref22 << 10) | (uint32_t)sctl[0];
            const int need_eq = sctl[1];

            uint16_t* cidx = (uint16_t*)cc;     // scratch reuse
            if (tid == 0) sW = 0;
            __syncthreads();
            for (int i = tid; i < KC; i += NT) {
                uint32_t k2 = fkey(__float_as_uint(in1[i]));
                if (k2 > T) atomicOr(&bitmap[i >> 5], 1u << (i & 31));
                else if (k2 == T) {
                    int pos = atomicAdd(&sW, 1);
                    if (pos < CAP) cidx[pos] = (uint16_t)i;
                }
            }
            __syncthreads();
            int We = min(sW, CAP);
            for (int i = tid; i < We; i += NT) {
                int di = cidx[i];
                int rank = 0;
                for (int j = 0; j < We; j++) rank += ((int)cidx[j] < di);
                if (rank < need_eq) atomicOr(&bitmap[di >> 5], 1u << (di & 31));
            }
            __syncthreads();
        }
    }

    // ---- Emission: bitmap popcount + block prefix scan + bit walk ----
    uint32_t wbits = bitmap[tid];
    int cnt = __popc(wbits);
    int pos = block_prefix_excl(cnt, tid, wtmp);

    float* __restrict__ bs_out  = out;
    float* __restrict__ cls_out = out + (size_t)BSZ * MAXC;
    float* __restrict__ msk_out = out + (size_t)2 * BSZ * MAXC;
    const size_t rbase = (size_t)row * MAXC;

    while (wbits) {
        int bit = __ffs(wbits) - 1;
        wbits &= wbits - 1;
        cls_out[rbase + pos] = (float)(tid * 32 + bit);
        pos++;
    }

    // ---- Padding / bs_idx / mask ----
    if (tid < MAXC) {
        bs_out[rbase + tid] = (tid < ktrain) ? (float)row : -1.0f;
        if (tid >= ktrain) cls_out[rbase + tid] = -1.0f;
        msk_out[rbase + tid] = (tid < ktrain) ? 1.0f : 0.0f;
    }
}

extern "C" void kernel_launch(void* const* d_in, const int* in_sizes, int n_in,
                              void* d_out, int out_size)
{
    const float* logits = (const float*)d_in[0];
    float* out = (float*)d_out;
    retention_kernel<<<BSZ, NT>>>(logits, out);
}